// round 2
// baseline (speedup 1.0000x reference)
#include <cuda_runtime.h>
#include <math.h>

#define NMOL   32
#define NATOM  128
#define DEG    32
#define NTOT   4096
#define NPAIR  131072
#define NSENS  20
#define NF1    20
#define TM     32          // atoms owned per k_step block
#define ETS    36          // padded envT row stride (conflict-free STS, float4-aligned)

// ---------------- scratch (device globals; no allocation) ----------------
__device__ float g_sense[NPAIR * NSENS];     // [pair][s]
__device__ float g_indf [NTOT * 5];          // [atom][5]
__device__ float g_ct   [NTOT * NF1];        // in-place (owner block only)
__device__ float g_h    [2 * NTOT * NF1];    // parity double buffer
__device__ float g_x0   [2 * NTOT];          // parity double buffer

__device__ __forceinline__ float softplusf(float x) {
    return fmaxf(x, 0.f) + log1pf(expf(-fabsf(x)));
}
__device__ __forceinline__ float sigmoidf(float x) {
    return 1.f / (1.f + expf(-x));
}

// ---------------- one-time prep ----------------
__global__ void k_indf(const int* __restrict__ species, const float* __restrict__ x_h) {
    int n = blockIdx.x * blockDim.x + threadIdx.x;
    if (n >= NTOT) return;
    int sp = species[n];
    g_indf[n * 5 + 0] = (sp == 1) ? 1.f : 0.f;
    g_indf[n * 5 + 1] = (sp == 8) ? 1.f : 0.f;
    g_indf[n * 5 + 2] = x_h[n * 3 + 0];
    g_indf[n * 5 + 3] = x_h[n * 3 + 1];
    g_indf[n * 5 + 4] = x_h[n * 3 + 2];
}

__global__ void k_sense(const float* __restrict__ coord, const int* __restrict__ ps) {
    int p = blockIdx.x * blockDim.x + threadIdx.x;
    if (p >= NPAIR) return;
    int a = p >> 5;
    int b = ps[p];
    float dx = coord[a * 3 + 0] - coord[b * 3 + 0];
    float dy = coord[a * 3 + 1] - coord[b * 3 + 1];
    float dz = coord[a * 3 + 2] - coord[b * 3 + 2];
    float d = sqrtf(dx * dx + dy * dy + dz * dz + 1e-12f);
    float cut = 0.f;
    if (d < 7.5f) { float c = cospif(d * (1.f / 15.f)); cut = c * c; }
    float invd = 1.f / d;
    const float m0 = 0.2f;
    const float m1 = 1.f / 0.7f;
    const float dmu = (m1 - m0) / 19.f;
    const float invsig = 20.f / (m1 - m0);
#pragma unroll
    for (int s = 0; s < NSENS; s++) {
        float z = (invd - (m0 + s * dmu)) * invsig;
        g_sense[p * NSENS + s] = expf(-0.5f * z * z) * cut;
    }
}

// ---------------- f0 hipnn (runs once): writes c_t, g_h[0] ----------------
__global__ void k_f0(const int* __restrict__ ps,
                     const float* __restrict__ iw, const float* __restrict__ sw,
                     const float* __restrict__ sb, const float* __restrict__ aw,
                     const float* __restrict__ ab) {
    __shared__ float ss[32 * 20];
    __shared__ float sX[32 * 5];
    __shared__ float senv[100];
    __shared__ float sy[40];
    __shared__ float sx[5];
    int a = blockIdx.x;
    int t = threadIdx.x;  // 64 threads

    for (int i = t; i < 640; i += 64) ss[i] = g_sense[a * 640 + i];
    if (t < 32) {
        int nb = ps[a * 32 + t];
#pragma unroll
        for (int f = 0; f < 5; f++) sX[t * 5 + f] = g_indf[nb * 5 + f];
    }
    if (t < 5) sx[t] = g_indf[a * 5 + t];
    __syncthreads();

    for (int e = t; e < 100; e += 64) {
        int s = e / 5, f = e % 5;
        float acc = 0.f;
        for (int k = 0; k < 32; k++) acc += ss[k * 20 + s] * sX[k * 5 + f];
        senv[e] = acc;
    }
    __syncthreads();

    if (t < 40) {
        float pre = sb[t];
        for (int e = 0; e < 100; e++) pre += senv[e] * iw[e * 40 + t];
#pragma unroll
        for (int f = 0; f < 5; f++) pre += sx[f] * sw[f * 40 + t];
        sy[t] = softplusf(pre);
    }
    __syncthreads();

    for (int l = 0; l < 3; l++) {
        float v = 0.f;
        if (t < 40) {
            v = ab[l * 40 + t];
            for (int j = 0; j < 40; j++) v += sy[j] * aw[(l * 40 + j) * 40 + t];
            v = softplusf(v);
        }
        __syncthreads();
        if (t < 40) sy[t] = v;
        __syncthreads();
    }
    if (t < 20) {
        g_ct[a * 20 + t] = sy[t];
        g_h[a * 20 + t]  = sy[20 + t];   // parity buffer 0
    }
}

// ---------------- fused per-step kernel ----------------
// SMEM floats:
//   s_xcat[5120] | s_envT[28800] | s_work[20480] | s_nb[1024 int] | s_xin[128] | s_h1w[1700]
// s_work overlays:
//   phase2: senv[0,2560) sy[2560,5120) sy2[5120,7680)
//   phase3: sense tile [0,20480)
//   GEMM:   s_wc[0,10240) s_tmp[10240,12800) s_o[12800,13440)
#define SMEM_FLOATS (5120 + 28800 + 20480 + 1024 + 128 + 1700)
#define SMEM_BYTES  (SMEM_FLOATS * 4)

__global__ void __launch_bounds__(256, 1)
k_step(const int* __restrict__ ps, const float* __restrict__ x_raw, int mode,
       const float* __restrict__ h1_iw, const float* __restrict__ h1_sw,
       const float* __restrict__ h1_sb, const float* __restrict__ h1_aw,
       const float* __restrict__ h1_ab,
       const float* __restrict__ Wint, const float* __restrict__ Wself,
       const float* __restrict__ Wb,
       const float* __restrict__ pw0, const float* __restrict__ pw1,
       const float* __restrict__ pb1,
       int outcol, float* __restrict__ out, int parity) {
    extern __shared__ float sm[];
    float* s_xcat = sm;                                   // 5120
    float* s_envT = sm + 5120;                            // 28800
    float* s_work = sm + 5120 + 28800;                    // 20480
    int*   s_nb   = (int*)(sm + 5120 + 28800 + 20480);    // 1024 ints
    float* s_xin  = sm + 5120 + 28800 + 20480 + 1024;     // 128
    float* s_h1w  = s_xin + 128;                          // 1700
    float* s_iw = s_h1w;            // 400
    float* s_sw = s_h1w + 400;      // 20
    float* s_sb = s_h1w + 420;      // 20
    float* s_aw = s_h1w + 440;      // 1200
    float* s_ab = s_h1w + 1640;     // 60

    float* senv = s_work;
    float* sy   = s_work + 2560;
    float* sy2  = s_work + 5120;
    float* s_wc  = s_work;
    float* s_tmp = s_work + 10240;
    float* s_o   = s_work + 12800;

    int t  = threadIdx.x;
    int A0 = blockIdx.x * TM;
    int MB = (A0 / NATOM) * NATOM;
    int L0 = A0 - MB;
    const float* x0_r = g_x0 + parity * NTOT;
    float*       x0_w = g_x0 + (parity ^ 1) * NTOT;
    const float* h_r  = g_h + parity * (NTOT * NF1);
    float*       h_w  = g_h + (parity ^ 1) * (NTOT * NF1);

    // ---- stage: x_in, h -> xcat h-slots, h1 weights, my nb ----
    if (t < 128) {
        int n = MB + t;
        s_xin[t] = (mode < 2) ? x_raw[n * 2 + mode] : x0_r[n];
    }
    {
        const float4* hsrc = (const float4*)(h_r + MB * NF1);
        for (int i4 = t; i4 < 640; i4 += 256) {
            int a = i4 / 5, j = (i4 % 5) * 4;
            *(float4*)&s_xcat[a * 40 + 20 + j] = hsrc[i4];
        }
    }
    for (int i = t; i < 400;  i += 256) s_iw[i] = h1_iw[i];
    for (int i = t; i < 1200; i += 256) s_aw[i] = h1_aw[i];
    if (t < 20) { s_sw[t] = h1_sw[t]; s_sb[t] = h1_sb[t]; }
    if (t >= 32 && t < 32 + 60) s_ab[t - 32] = h1_ab[t - 32];
    for (int i = t; i < 1024; i += 256) s_nb[i] = ps[A0 * 32 + i] - MB;
    __syncthreads();

    // ---- phase 2: x_t hipnn for all 128 molecule atoms (2 threads/atom) ----
    {
        int a  = t >> 1;
        int sh = (t & 1) * 10;
        int p0 = (MB + a) * 32;
        float acc[10];
#pragma unroll
        for (int s = 0; s < 10; s++) acc[s] = 0.f;
        for (int k = 0; k < 32; k++) {
            int nb = ps[p0 + k] - MB;
            float xv = s_xin[nb];
            const float* sp = g_sense + (size_t)(p0 + k) * 20 + sh;
#pragma unroll
            for (int s = 0; s < 10; s++) acc[s] += sp[s] * xv;
        }
#pragma unroll
        for (int s = 0; s < 10; s++) senv[a * 20 + sh + s] = acc[s];
        __syncthreads();

        float xo = s_xin[a];
        float pre[10];
#pragma unroll
        for (int j = 0; j < 10; j++) pre[j] = s_sb[sh + j] + xo * s_sw[sh + j];
        for (int s2 = 0; s2 < 20; s2++) {
            float ev = senv[a * 20 + s2];
#pragma unroll
            for (int j = 0; j < 10; j++) pre[j] += ev * s_iw[s2 * 20 + sh + j];
        }
#pragma unroll
        for (int j = 0; j < 10; j++) sy[a * 20 + sh + j] = softplusf(pre[j]);
        __syncthreads();

        float* src = sy; float* dst = sy2;
        for (int l = 0; l < 3; l++) {
            float v[10];
#pragma unroll
            for (int j = 0; j < 10; j++) v[j] = s_ab[l * 20 + sh + j];
            for (int i2 = 0; i2 < 20; i2++) {
                float yv = src[a * 20 + i2];
#pragma unroll
                for (int j = 0; j < 10; j++) v[j] += yv * s_aw[(l * 20 + i2) * 20 + sh + j];
            }
            __syncthreads();
#pragma unroll
            for (int j = 0; j < 10; j++) dst[a * 20 + sh + j] = softplusf(v[j]);
            __syncthreads();
            float* tp = src; src = dst; dst = tp;
        }
        // x_t -> xcat slots [0,20)
#pragma unroll
        for (int j = 0; j < 10; j++) s_xcat[a * 40 + sh + j] = src[a * 20 + sh + j];
    }

    // ---- phase 3: sense tile for my 32 atoms, then env ----
    {
        const float4* ssrc = (const float4*)(g_sense + (size_t)A0 * 640);
        float4* sdst = (float4*)s_work;
        __syncthreads();             // phase-2 reads of s_work done
        for (int i = t; i < 5120; i += 256) sdst[i] = ssrc[i];
    }
    __syncthreads();

    {
        int i  = t >> 3;
        int f0 = (t & 7) * 5;
        float acc[20][5];
#pragma unroll
        for (int s = 0; s < 20; s++)
#pragma unroll
            for (int j = 0; j < 5; j++) acc[s][j] = 0.f;
        const float* sen = s_work + i * 640;
        const int* nbp = s_nb + i * 32;
        for (int k = 0; k < 32; k++) {
            int nb = nbp[k];
            const float* xr = s_xcat + nb * 40 + f0;
            float x0v = xr[0], x1v = xr[1], x2v = xr[2], x3v = xr[3], x4v = xr[4];
            const float* sk = sen + k * 20;
#pragma unroll
            for (int s = 0; s < 20; s++) {
                float sv = sk[s];
                acc[s][0] += sv * x0v;
                acc[s][1] += sv * x1v;
                acc[s][2] += sv * x2v;
                acc[s][3] += sv * x3v;
                acc[s][4] += sv * x4v;
            }
        }
#pragma unroll
        for (int s = 0; s < 20; s++)
#pragma unroll
            for (int j = 0; j < 5; j++)
                s_envT[(s * 40 + f0 + j) * ETS + i] = acc[s][j];
    }
    __syncthreads();   // sense reads done + envT visible

    // ---- phase 4: GEMM (32x80) = envT(32x800) @ Wint(800x80), reg-prefetch pipeline
    float a00=0,a01=0,a02=0,a03=0, a10=0,a11=0,a12=0,a13=0,
          a20=0,a21=0,a22=0,a23=0, a30=0,a31=0,a32=0,a33=0;
    bool active = (t < 160);
    int i0 = active ? (t / 20) * 4 : 0;
    int g0 = active ? (t % 20) * 4 : 0;
    const float4* W4 = (const float4*)Wint;

    {   // stage chunk 0 (128 rows)
        for (int i = t; i < 2560; i += 256) ((float4*)s_wc)[i] = W4[i];
    }
    __syncthreads();

    for (int c = 0; c < 7; c++) {
        int e0 = c * 128;
        int elen = (c < 6) ? 128 : 32;
        // prefetch next chunk into registers
        float4 pf[10];
        int nb4 = 0, pbase = 0;
        if (c < 6) {
            nb4 = ((c + 1 < 6) ? 128 : 32) * 20;
            pbase = (e0 + 128) * 20;
#pragma unroll
            for (int q = 0; q < 10; q++) {
                int i = t + q * 256;
                if (i < nb4) pf[q] = W4[pbase + i];
            }
        }
        if (active) {
            for (int e = 0; e < elen; e++) {
                float4 ev = *(const float4*)&s_envT[(e0 + e) * ETS + i0];
                float4 wv = *(const float4*)&s_wc[e * 80 + g0];
                a00 += ev.x * wv.x; a01 += ev.x * wv.y; a02 += ev.x * wv.z; a03 += ev.x * wv.w;
                a10 += ev.y * wv.x; a11 += ev.y * wv.y; a12 += ev.y * wv.z; a13 += ev.y * wv.w;
                a20 += ev.z * wv.x; a21 += ev.z * wv.y; a22 += ev.z * wv.z; a23 += ev.z * wv.w;
                a30 += ev.w * wv.x; a31 += ev.w * wv.y; a32 += ev.w * wv.z; a33 += ev.w * wv.w;
            }
        }
        __syncthreads();
        if (c < 6) {
#pragma unroll
            for (int q = 0; q < 10; q++) {
                int i = t + q * 256;
                if (i < nb4) ((float4*)s_wc)[i] = pf[q];
            }
            __syncthreads();
        }
    }

    if (active) {
        float4 bv = *(const float4*)&Wb[g0];
        a00 += bv.x; a01 += bv.y; a02 += bv.z; a03 += bv.w;
        a10 += bv.x; a11 += bv.y; a12 += bv.z; a13 += bv.w;
        a20 += bv.x; a21 += bv.y; a22 += bv.z; a23 += bv.w;
        a30 += bv.x; a31 += bv.y; a32 += bv.z; a33 += bv.w;
        const float* xc0 = s_xcat + (L0 + i0 + 0) * 40;
        const float* xc1 = s_xcat + (L0 + i0 + 1) * 40;
        const float* xc2 = s_xcat + (L0 + i0 + 2) * 40;
        const float* xc3 = s_xcat + (L0 + i0 + 3) * 40;
#pragma unroll
        for (int f = 0; f < 40; f++) {
            float4 wv = *(const float4*)&Wself[f * 80 + g0];
            float x0v = xc0[f], x1v = xc1[f], x2v = xc2[f], x3v = xc3[f];
            a00 += x0v * wv.x; a01 += x0v * wv.y; a02 += x0v * wv.z; a03 += x0v * wv.w;
            a10 += x1v * wv.x; a11 += x1v * wv.y; a12 += x1v * wv.z; a13 += x1v * wv.w;
            a20 += x2v * wv.x; a21 += x2v * wv.y; a22 += x2v * wv.z; a23 += x2v * wv.w;
            a30 += x3v * wv.x; a31 += x3v * wv.y; a32 += x3v * wv.z; a33 += x3v * wv.w;
        }
        float* d0 = &s_tmp[(i0 + 0) * 80 + g0];
        float* d1 = &s_tmp[(i0 + 1) * 80 + g0];
        float* d2 = &s_tmp[(i0 + 2) * 80 + g0];
        float* d3 = &s_tmp[(i0 + 3) * 80 + g0];
        d0[0]=a00; d0[1]=a01; d0[2]=a02; d0[3]=a03;
        d1[0]=a10; d1[1]=a11; d1[2]=a12; d1[3]=a13;
        d2[0]=a20; d2[1]=a21; d2[2]=a22; d2[3]=a23;
        d3[0]=a30; d3[1]=a31; d3[2]=a32; d3[3]=a33;
    }
    __syncthreads();

    // ---- phase 5: gates ----
    for (int idx = t; idx < TM * 20; idx += 256) {
        int i = idx / 20, j = idx % 20;
        int a = A0 + i;
        float t0v = s_tmp[i * 80 + j * 4 + 0];
        float t1v = s_tmp[i * 80 + j * 4 + 1];
        float t2v = s_tmp[i * 80 + j * 4 + 2];
        float t3v = s_tmp[i * 80 + j * 4 + 3];
        float o  = sigmoidf(t3v);
        float cn = sigmoidf(t1v) * g_ct[a * 20 + j] + sigmoidf(t0v) * tanhf(t2v);
        g_ct[a * 20 + j] = cn;
        h_w[a * 20 + j]  = o * tanhf(cn);
        s_o[i * 20 + j] = o;
    }
    __syncthreads();

    // ---- x0 epilogue (+ output column for steps 2..4) ----
    if (t < TM) {
        int a = A0 + t;
        float x0v = pb1[0];
#pragma unroll
        for (int f = 0; f < 5; f++)  x0v += g_indf[a * 5 + f] * pw0[f];
#pragma unroll
        for (int j = 0; j < 20; j++) x0v += s_o[t * 20 + j] * pw1[j];
        x0_w[a] = x0v;
        if (outcol >= 0) out[a * 3 + outcol] = x0v;
    }
}

// ---------------- host ----------------
extern "C" void kernel_launch(void* const* d_in, const int* in_sizes, int n_in,
                              void* d_out, int out_size) {
    const int*   species = (const int*)d_in[0];
    const float* coords  = (const float*)d_in[1];
    const float* x_h     = (const float*)d_in[2];
    const float* x_raw   = (const float*)d_in[3];
    const int*   ps      = (const int*)d_in[5];
    const float* h0_iw   = (const float*)d_in[6];
    const float* h0_sw   = (const float*)d_in[7];
    const float* h0_sb   = (const float*)d_in[8];
    const float* h0_aw   = (const float*)d_in[9];
    const float* h0_ab   = (const float*)d_in[10];
    const float* h1_iw   = (const float*)d_in[11];
    const float* h1_sw   = (const float*)d_in[12];
    const float* h1_sb   = (const float*)d_in[13];
    const float* h1_aw   = (const float*)d_in[14];
    const float* h1_ab   = (const float*)d_in[15];
    const float* W_iw    = (const float*)d_in[16];
    const float* W_sw    = (const float*)d_in[17];
    const float* W_sb    = (const float*)d_in[18];
    const float* pw0     = (const float*)d_in[19];
    const float* pw1     = (const float*)d_in[20];
    const float* pb1     = (const float*)d_in[21];
    float* out = (float*)d_out;

    static int smem_set = 0;
    if (!smem_set) {
        cudaFuncSetAttribute(k_step, cudaFuncAttributeMaxDynamicSharedMemorySize, SMEM_BYTES);
        smem_set = 1;
    }

    k_indf<<<(NTOT + 255) / 256, 256>>>(species, x_h);
    k_sense<<<NPAIR / 256, 256>>>(coords, ps);
    k_f0<<<NTOT, 64>>>(ps, h0_iw, h0_sw, h0_sb, h0_aw, h0_ab);

    for (int s = 0; s < 5; s++) {
        int mode = (s < 2) ? s : 2;
        int outcol = (s >= 2) ? (s - 2) : -1;
        k_step<<<NTOT / TM, 256, SMEM_BYTES>>>(ps, x_raw, mode,
                                               h1_iw, h1_sw, h1_sb, h1_aw, h1_ab,
                                               W_iw, W_sw, W_sb,
                                               pw0, pw1, pb1,
                                               outcol, out, s & 1);
    }
}

// round 3
// speedup vs baseline: 2.1650x; 2.1650x over previous
#include <cuda_runtime.h>
#include <math.h>

#define NMOL   32
#define NATOM  128
#define DEG    32
#define NTOT   4096
#define NPAIR  131072
#define NSENS  20
#define NF1    20
#define TM     32          // atoms owned per k_step block
#define ETS    36          // padded envT row stride
#define SROW   648         // padded sense row (floats) = 162 float4

// ---------------- scratch (device globals; no allocation) ----------------
__device__ float g_sense[NPAIR * NSENS];     // [pair][s]
__device__ float g_indf [NTOT * 5];          // [atom][5]
__device__ float g_ct   [NTOT * NF1];        // in-place (owner block only)
__device__ float g_h    [2 * NTOT * NF1];    // parity double buffer
__device__ float g_x0   [2 * NTOT];          // parity double buffer

__device__ __forceinline__ float softplusf(float x) {
    return fmaxf(x, 0.f) + log1pf(expf(-fabsf(x)));
}
__device__ __forceinline__ float sigmoidf(float x) {
    return 1.f / (1.f + expf(-x));
}

// ---------------- one-time prep ----------------
__global__ void k_indf(const int* __restrict__ species, const float* __restrict__ x_h) {
    int n = blockIdx.x * blockDim.x + threadIdx.x;
    if (n >= NTOT) return;
    int sp = species[n];
    g_indf[n * 5 + 0] = (sp == 1) ? 1.f : 0.f;
    g_indf[n * 5 + 1] = (sp == 8) ? 1.f : 0.f;
    g_indf[n * 5 + 2] = x_h[n * 3 + 0];
    g_indf[n * 5 + 3] = x_h[n * 3 + 1];
    g_indf[n * 5 + 4] = x_h[n * 3 + 2];
}

__global__ void k_sense(const float* __restrict__ coord, const int* __restrict__ ps) {
    int p = blockIdx.x * blockDim.x + threadIdx.x;
    if (p >= NPAIR) return;
    int a = p >> 5;
    int b = ps[p];
    float dx = coord[a * 3 + 0] - coord[b * 3 + 0];
    float dy = coord[a * 3 + 1] - coord[b * 3 + 1];
    float dz = coord[a * 3 + 2] - coord[b * 3 + 2];
    float d = sqrtf(dx * dx + dy * dy + dz * dz + 1e-12f);
    float cut = 0.f;
    if (d < 7.5f) { float c = cospif(d * (1.f / 15.f)); cut = c * c; }
    float invd = 1.f / d;
    const float m0 = 0.2f;
    const float m1 = 1.f / 0.7f;
    const float dmu = (m1 - m0) / 19.f;
    const float invsig = 20.f / (m1 - m0);
#pragma unroll
    for (int s = 0; s < NSENS; s++) {
        float z = (invd - (m0 + s * dmu)) * invsig;
        g_sense[p * NSENS + s] = expf(-0.5f * z * z) * cut;
    }
}

// ---------------- f0 hipnn (runs once): writes c_t, g_h[0] ----------------
__global__ void k_f0(const int* __restrict__ ps,
                     const float* __restrict__ iw, const float* __restrict__ sw,
                     const float* __restrict__ sb, const float* __restrict__ aw,
                     const float* __restrict__ ab) {
    __shared__ float ss[32 * 20];
    __shared__ float sX[32 * 5];
    __shared__ float senv[100];
    __shared__ float sy[40];
    __shared__ float sx[5];
    int a = blockIdx.x;
    int t = threadIdx.x;  // 64 threads

    for (int i = t; i < 640; i += 64) ss[i] = g_sense[a * 640 + i];
    if (t < 32) {
        int nb = ps[a * 32 + t];
#pragma unroll
        for (int f = 0; f < 5; f++) sX[t * 5 + f] = g_indf[nb * 5 + f];
    }
    if (t < 5) sx[t] = g_indf[a * 5 + t];
    __syncthreads();

    for (int e = t; e < 100; e += 64) {
        int s = e / 5, f = e % 5;
        float acc = 0.f;
        for (int k = 0; k < 32; k++) acc += ss[k * 20 + s] * sX[k * 5 + f];
        senv[e] = acc;
    }
    __syncthreads();

    if (t < 40) {
        float pre = sb[t];
        for (int e = 0; e < 100; e++) pre += senv[e] * iw[e * 40 + t];
#pragma unroll
        for (int f = 0; f < 5; f++) pre += sx[f] * sw[f * 40 + t];
        sy[t] = softplusf(pre);
    }
    __syncthreads();

    for (int l = 0; l < 3; l++) {
        float v = 0.f;
        if (t < 40) {
            v = ab[l * 40 + t];
            for (int j = 0; j < 40; j++) v += sy[j] * aw[(l * 40 + j) * 40 + t];
            v = softplusf(v);
        }
        __syncthreads();
        if (t < 40) sy[t] = v;
        __syncthreads();
    }
    if (t < 20) {
        g_ct[a * 20 + t] = sy[t];
        g_h[a * 20 + t]  = sy[20 + t];   // parity buffer 0
    }
}

// ---------------- fused per-step kernel ----------------
// SMEM (floats):
//   s_xcat [0,5120) | s_envT [5120,33920) | s_work [33920,54656)=32xSROW
//   s_nb ints [54656,55680) | s_xin [55680,55808) | s_h1w [55808,57508)
// s_envT overlay in phase 2: senvM[0,2560) sy[2560,5120) sy2[5120,7680)
// s_work overlay in GEMM:    s_wc[0,10240) s_tmp[10240,12800) s_o[12800,13440)
#define SMEM_FLOATS (5120 + 28800 + 32 * SROW + 1024 + 128 + 1700)
#define SMEM_BYTES  (SMEM_FLOATS * 4)

__global__ void __launch_bounds__(256, 1)
k_step(const int* __restrict__ ps, const float* __restrict__ x_raw, int mode,
       const float* __restrict__ h1_iw, const float* __restrict__ h1_sw,
       const float* __restrict__ h1_sb, const float* __restrict__ h1_aw,
       const float* __restrict__ h1_ab,
       const float* __restrict__ Wint, const float* __restrict__ Wself,
       const float* __restrict__ Wb,
       const float* __restrict__ pw0, const float* __restrict__ pw1,
       const float* __restrict__ pb1,
       int outcol, float* __restrict__ out, int parity) {
    extern __shared__ float sm[];
    float* s_xcat = sm;                                    // 5120
    float* s_envT = sm + 5120;                             // 28800
    float* s_work = sm + 5120 + 28800;                     // 32*SROW
    int*   s_nb   = (int*)(sm + 5120 + 28800 + 32 * SROW); // 1024 ints
    float* s_xin  = sm + 5120 + 28800 + 32 * SROW + 1024;  // 128
    float* s_h1w  = s_xin + 128;                           // 1700
    float* s_iw = s_h1w;            // 400
    float* s_sw = s_h1w + 400;      // 20
    float* s_sb = s_h1w + 420;      // 20
    float* s_aw = s_h1w + 440;      // 1200
    float* s_ab = s_h1w + 1640;     // 60

    float* senvM = s_envT;          // phase 2: [128][20]
    float* sy    = s_envT + 2560;
    float* sy2   = s_envT + 5120;
    float* s_wc  = s_work;          // GEMM W chunk (10240)
    float* s_tmp = s_work + 10240;  // 2560
    float* s_o   = s_work + 12800;  // 640

    int t  = threadIdx.x;
    int A0 = blockIdx.x * TM;
    int MB = (A0 / NATOM) * NATOM;
    int L0 = A0 - MB;
    int myc = L0 >> 5;              // my 32-atom chunk index within molecule
    const float* x0_r = g_x0 + parity * NTOT;
    float*       x0_w = g_x0 + (parity ^ 1) * NTOT;
    const float* h_r  = g_h + parity * (NTOT * NF1);
    float*       h_w  = g_h + (parity ^ 1) * (NTOT * NF1);

    // ---- stage: x_in (molecule), h -> xcat h-slots, h1 weights, my nb ----
    if (t < 128) {
        int n = MB + t;
        s_xin[t] = (mode < 2) ? x_raw[n * 2 + mode] : x0_r[n];
    }
    {
        const float4* hsrc = (const float4*)(h_r + MB * NF1);
        for (int i4 = t; i4 < 640; i4 += 256) {
            int a = i4 / 5, j = (i4 % 5) * 4;
            *(float4*)&s_xcat[a * 40 + 20 + j] = hsrc[i4];
        }
    }
    for (int i = t; i < 400;  i += 256) s_iw[i] = h1_iw[i];
    for (int i = t; i < 1200; i += 256) s_aw[i] = h1_aw[i];
    if (t < 20) { s_sw[t] = h1_sw[t]; s_sb[t] = h1_sb[t]; }
    if (t >= 64 && t < 124) s_ab[t - 64] = h1_ab[t - 64];
    for (int i = t; i < 1024; i += 256) s_nb[i] = ps[A0 * 32 + i] - MB;
    __syncthreads();

    // ---- phase 2a: env (f=1) for all 128 molecule atoms, chunked + coalesced ----
    // process chunks ending with myc so phase 3 reuses the staged sense tile
    for (int cc = 0; cc < 4; cc++) {
        int c = (myc + 1 + cc) & 3;
        if (cc) __syncthreads();   // previous chunk's sense reads done
        {   // stage sense for atoms [MB + c*32, +32): 32 rows x 160 float4, stride 162
            const float4* src = (const float4*)(g_sense + (size_t)(MB + c * 32) * 640);
            float4* dst = (float4*)s_work;
            for (int q = 0; q < 20; q++) {
                int i = t + q * 256;
                int row = i / 160, col = i - row * 160;
                dst[row * 162 + col] = src[i];
            }
        }
        __syncthreads();
        int aL = t >> 3;           // atom in chunk
        int r  = t & 7;            // k-lane
        int aM = c * 32 + aL;      // molecule-local atom
        float acc[20];
#pragma unroll
        for (int s = 0; s < 20; s++) acc[s] = 0.f;
#pragma unroll
        for (int j = 0; j < 4; j++) {
            int k = r + j * 8;
            int nb = ps[(MB + aM) * 32 + k] - MB;
            float xv = s_xin[nb];
            const float4* sp = (const float4*)(s_work + aL * SROW + k * 20);
#pragma unroll
            for (int q = 0; q < 5; q++) {
                float4 sv = sp[q];
                acc[q * 4 + 0] += sv.x * xv;
                acc[q * 4 + 1] += sv.y * xv;
                acc[q * 4 + 2] += sv.z * xv;
                acc[q * 4 + 3] += sv.w * xv;
            }
        }
#pragma unroll
        for (int d = 4; d >= 1; d >>= 1)
#pragma unroll
            for (int s = 0; s < 20; s++)
                acc[s] += __shfl_down_sync(0xFFFFFFFFu, acc[s], d);
        if (r == 0) {
#pragma unroll
            for (int s = 0; s < 20; s++) senvM[aM * 20 + s] = acc[s];
        }
    }
    __syncthreads();

    // ---- phase 2b: x_t MLP for all 128 atoms (2 threads/atom) ----
    {
        int a  = t >> 1;
        int sh = (t & 1) * 10;
        float xo = s_xin[a];
        float pre[10];
#pragma unroll
        for (int j = 0; j < 10; j++) pre[j] = s_sb[sh + j] + xo * s_sw[sh + j];
        for (int s2 = 0; s2 < 20; s2++) {
            float ev = senvM[a * 20 + s2];
#pragma unroll
            for (int j = 0; j < 10; j++) pre[j] += ev * s_iw[s2 * 20 + sh + j];
        }
#pragma unroll
        for (int j = 0; j < 10; j++) sy[a * 20 + sh + j] = softplusf(pre[j]);
        __syncthreads();

        float* src = sy; float* dst = sy2;
        for (int l = 0; l < 3; l++) {
            float v[10];
#pragma unroll
            for (int j = 0; j < 10; j++) v[j] = s_ab[l * 20 + sh + j];
            for (int i2 = 0; i2 < 20; i2++) {
                float yv = src[a * 20 + i2];
#pragma unroll
                for (int j = 0; j < 10; j++) v[j] += yv * s_aw[(l * 20 + i2) * 20 + sh + j];
            }
            __syncthreads();
#pragma unroll
            for (int j = 0; j < 10; j++) dst[a * 20 + sh + j] = softplusf(v[j]);
            __syncthreads();
            float* tp = src; src = dst; dst = tp;
        }
#pragma unroll
        for (int j = 0; j < 10; j++) s_xcat[a * 40 + sh + j] = src[a * 20 + sh + j];
    }
    __syncthreads();

    // ---- phase 3: env (40 features) for my 32 atoms (sense tile already staged) ----
    {
        int i  = t >> 3;
        int f0 = (t & 7) * 5;
        float acc[20][5];
#pragma unroll
        for (int s = 0; s < 20; s++)
#pragma unroll
            for (int j = 0; j < 5; j++) acc[s][j] = 0.f;
        const float* sen = s_work + i * SROW;
        const int* nbp = s_nb + i * 32;
        for (int k = 0; k < 32; k++) {
            int nb = nbp[k];
            const float* xr = s_xcat + nb * 40 + f0;
            float x0v = xr[0], x1v = xr[1], x2v = xr[2], x3v = xr[3], x4v = xr[4];
            const float4* sk = (const float4*)(sen + k * 20);
#pragma unroll
            for (int q = 0; q < 5; q++) {
                float4 sv = sk[q];
#pragma unroll
                for (int cpt = 0; cpt < 4; cpt++) {
                    float svc = (cpt == 0) ? sv.x : (cpt == 1) ? sv.y : (cpt == 2) ? sv.z : sv.w;
                    int s = q * 4 + cpt;
                    acc[s][0] += svc * x0v;
                    acc[s][1] += svc * x1v;
                    acc[s][2] += svc * x2v;
                    acc[s][3] += svc * x3v;
                    acc[s][4] += svc * x4v;
                }
            }
        }
#pragma unroll
        for (int s = 0; s < 20; s++)
#pragma unroll
            for (int j = 0; j < 5; j++)
                s_envT[(s * 40 + f0 + j) * ETS + i] = acc[s][j];
    }
    __syncthreads();   // sense reads done + envT visible; s_work free for s_wc

    // ---- phase 4: GEMM (32x80) = envT(32x800) @ Wint(800x80), 2x5 tiles, 256 thr ----
    float a0[10];
#pragma unroll
    for (int j = 0; j < 10; j++) a0[j] = 0.f;
    int g0 = (t & 15) * 5;
    int i0 = (t >> 4) * 2;
    const float4* W4 = (const float4*)Wint;

    for (int i = t; i < 2560; i += 256) ((float4*)s_wc)[i] = W4[i];  // chunk 0
    __syncthreads();

    for (int c = 0; c < 7; c++) {
        int e0 = c * 128;
        int elen = (c < 6) ? 128 : 32;
        float4 pf[10];
        int nb4 = 0, pbase = 0;
        if (c < 6) {
            nb4 = ((c + 1 < 6) ? 128 : 32) * 20;
            pbase = (e0 + 128) * 20;
#pragma unroll
            for (int q = 0; q < 10; q++) {
                int i = t + q * 256;
                if (i < nb4) pf[q] = W4[pbase + i];
            }
        }
        for (int e = 0; e < elen; e++) {
            float2 ev = *(const float2*)&s_envT[(e0 + e) * ETS + i0];
            const float* wr = &s_wc[e * 80 + g0];
            float w0 = wr[0], w1 = wr[1], w2 = wr[2], w3 = wr[3], w4 = wr[4];
            a0[0] += ev.x * w0; a0[1] += ev.x * w1; a0[2] += ev.x * w2;
            a0[3] += ev.x * w3; a0[4] += ev.x * w4;
            a0[5] += ev.y * w0; a0[6] += ev.y * w1; a0[7] += ev.y * w2;
            a0[8] += ev.y * w3; a0[9] += ev.y * w4;
        }
        __syncthreads();
        if (c < 6) {
#pragma unroll
            for (int q = 0; q < 10; q++) {
                int i = t + q * 256;
                if (i < nb4) ((float4*)s_wc)[i] = pf[q];
            }
            __syncthreads();
        }
    }

    // bias + self term + store to s_tmp
    {
        const float* wb = &Wb[g0];
        float b0 = wb[0], b1 = wb[1], b2 = wb[2], b3 = wb[3], b4 = wb[4];
        a0[0] += b0; a0[1] += b1; a0[2] += b2; a0[3] += b3; a0[4] += b4;
        a0[5] += b0; a0[6] += b1; a0[7] += b2; a0[8] += b3; a0[9] += b4;
        const float* xc0 = s_xcat + (L0 + i0 + 0) * 40;
        const float* xc1 = s_xcat + (L0 + i0 + 1) * 40;
#pragma unroll
        for (int f = 0; f < 40; f++) {
            const float* wr = &Wself[f * 80 + g0];
            float w0 = wr[0], w1 = wr[1], w2 = wr[2], w3 = wr[3], w4 = wr[4];
            float xa = xc0[f], xb = xc1[f];
            a0[0] += xa * w0; a0[1] += xa * w1; a0[2] += xa * w2;
            a0[3] += xa * w3; a0[4] += xa * w4;
            a0[5] += xb * w0; a0[6] += xb * w1; a0[7] += xb * w2;
            a0[8] += xb * w3; a0[9] += xb * w4;
        }
        float* d0 = &s_tmp[(i0 + 0) * 80 + g0];
        float* d1 = &s_tmp[(i0 + 1) * 80 + g0];
        d0[0] = a0[0]; d0[1] = a0[1]; d0[2] = a0[2]; d0[3] = a0[3]; d0[4] = a0[4];
        d1[0] = a0[5]; d1[1] = a0[6]; d1[2] = a0[7]; d1[3] = a0[8]; d1[4] = a0[9];
    }
    __syncthreads();

    // ---- phase 5: gates ----
    for (int idx = t; idx < TM * 20; idx += 256) {
        int i = idx / 20, j = idx % 20;
        int a = A0 + i;
        float t0v = s_tmp[i * 80 + j * 4 + 0];
        float t1v = s_tmp[i * 80 + j * 4 + 1];
        float t2v = s_tmp[i * 80 + j * 4 + 2];
        float t3v = s_tmp[i * 80 + j * 4 + 3];
        float o  = sigmoidf(t3v);
        float cn = sigmoidf(t1v) * g_ct[a * 20 + j] + sigmoidf(t0v) * tanhf(t2v);
        g_ct[a * 20 + j] = cn;
        h_w[a * 20 + j]  = o * tanhf(cn);
        s_o[i * 20 + j] = o;
    }
    __syncthreads();

    // ---- x0 epilogue (+ output column for steps 2..4) ----
    if (t < TM) {
        int a = A0 + t;
        float x0v = pb1[0];
#pragma unroll
        for (int f = 0; f < 5; f++)  x0v += g_indf[a * 5 + f] * pw0[f];
#pragma unroll
        for (int j = 0; j < 20; j++) x0v += s_o[t * 20 + j] * pw1[j];
        x0_w[a] = x0v;
        if (outcol >= 0) out[a * 3 + outcol] = x0v;
    }
}

// ---------------- host ----------------
extern "C" void kernel_launch(void* const* d_in, const int* in_sizes, int n_in,
                              void* d_out, int out_size) {
    const int*   species = (const int*)d_in[0];
    const float* coords  = (const float*)d_in[1];
    const float* x_h     = (const float*)d_in[2];
    const float* x_raw   = (const float*)d_in[3];
    const int*   ps      = (const int*)d_in[5];
    const float* h0_iw   = (const float*)d_in[6];
    const float* h0_sw   = (const float*)d_in[7];
    const float* h0_sb   = (const float*)d_in[8];
    const float* h0_aw   = (const float*)d_in[9];
    const float* h0_ab   = (const float*)d_in[10];
    const float* h1_iw   = (const float*)d_in[11];
    const float* h1_sw   = (const float*)d_in[12];
    const float* h1_sb   = (const float*)d_in[13];
    const float* h1_aw   = (const float*)d_in[14];
    const float* h1_ab   = (const float*)d_in[15];
    const float* W_iw    = (const float*)d_in[16];
    const float* W_sw    = (const float*)d_in[17];
    const float* W_sb    = (const float*)d_in[18];
    const float* pw0     = (const float*)d_in[19];
    const float* pw1     = (const float*)d_in[20];
    const float* pb1     = (const float*)d_in[21];
    float* out = (float*)d_out;

    static int smem_set = 0;
    if (!smem_set) {
        cudaFuncSetAttribute(k_step, cudaFuncAttributeMaxDynamicSharedMemorySize, SMEM_BYTES);
        smem_set = 1;
    }

    k_indf<<<(NTOT + 255) / 256, 256>>>(species, x_h);
    k_sense<<<NPAIR / 256, 256>>>(coords, ps);
    k_f0<<<NTOT, 64>>>(ps, h0_iw, h0_sw, h0_sb, h0_aw, h0_ab);

    for (int s = 0; s < 5; s++) {
        int mode = (s < 2) ? s : 2;
        int outcol = (s >= 2) ? (s - 2) : -1;
        k_step<<<NTOT / TM, 256, SMEM_BYTES>>>(ps, x_raw, mode,
                                               h1_iw, h1_sw, h1_sb, h1_aw, h1_ab,
                                               W_iw, W_sw, W_sb,
                                               pw0, pw1, pb1,
                                               outcol, out, s & 1);
    }
}

// round 6
// speedup vs baseline: 2.2443x; 1.0366x over previous
#include <cuda_runtime.h>
#include <math.h>

#define NMOL   32
#define NATOM  128
#define DEG    32
#define NTOT   4096
#define NPAIR  131072
#define NSENS  20
#define NF1    20
#define TM     32          // atoms owned per k_step block
#define EPS2   34          // envP row stride in u64 units (even -> 16B-aligned pairs)
#define SROW   648         // padded sense row (floats) = 162 float4

typedef unsigned long long u64t;

// ---------------- scratch (device globals; no allocation) ----------------
__device__ float  g_sense[NPAIR * NSENS];    // [pair][s]
__device__ float  g_indf [NTOT * 5];         // [atom][5]
__device__ float  g_ct   [NTOT * NF1];       // in-place (owner block only)
__device__ float  g_h    [2 * NTOT * NF1];   // parity double buffer
__device__ float  g_x0   [2 * NTOT];         // parity double buffer
__device__ float2 g_wpair [400 * 80];        // Wint paired over (s_even, s_odd)
__device__ float2 g_wspair[20 * 80];         // Wself paired over (f_even, f_odd)

__device__ __forceinline__ float softplusf(float x) {
    return fmaxf(x, 0.f) + log1pf(expf(-fabsf(x)));
}
__device__ __forceinline__ float sigmoidf(float x) {
    return 1.f / (1.f + expf(-x));
}
__device__ __forceinline__ u64t packdup(float x) {
    u64t r; asm("mov.b64 %0, {%1, %1};" : "=l"(r) : "f"(x)); return r;
}
__device__ __forceinline__ void ffma2(u64t& d, u64t a, u64t b) {
    asm("fma.rn.f32x2 %0, %1, %2, %0;" : "+l"(d) : "l"(a), "l"(b));
}
__device__ __forceinline__ void fadd2(u64t& d, u64t a) {
    asm("add.rn.f32x2 %0, %0, %1;" : "+l"(d) : "l"(a));
}
__device__ __forceinline__ void unpack2(u64t v, float& lo, float& hi) {
    asm("mov.b64 {%0, %1}, %2;" : "=f"(lo), "=f"(hi) : "l"(v));
}

// ---------------- one-time prep ----------------
__global__ void k_indf(const int* __restrict__ species, const float* __restrict__ x_h) {
    int n = blockIdx.x * blockDim.x + threadIdx.x;
    if (n >= NTOT) return;
    int sp = species[n];
    g_indf[n * 5 + 0] = (sp == 1) ? 1.f : 0.f;
    g_indf[n * 5 + 1] = (sp == 8) ? 1.f : 0.f;
    g_indf[n * 5 + 2] = x_h[n * 3 + 0];
    g_indf[n * 5 + 3] = x_h[n * 3 + 1];
    g_indf[n * 5 + 4] = x_h[n * 3 + 2];
}

__global__ void k_wprep(const float* __restrict__ Wint, const float* __restrict__ Wself) {
    int idx = blockIdx.x * 256 + threadIdx.x;
    if (idx < 32000) {
        int p = idx / 80, g = idx % 80;
        int s2 = p / 40, f = p % 40;
        int lo = 2 * s2 * 40 + f;
        g_wpair[idx] = make_float2(Wint[lo * 80 + g], Wint[(lo + 40) * 80 + g]);
    } else if (idx < 32000 + 1600) {
        int i2 = idx - 32000;
        int fp = i2 / 80, g = i2 % 80;
        g_wspair[i2] = make_float2(Wself[(2 * fp) * 80 + g], Wself[(2 * fp + 1) * 80 + g]);
    }
}

__global__ void k_sense(const float* __restrict__ coord, const int* __restrict__ ps) {
    int p = blockIdx.x * blockDim.x + threadIdx.x;
    if (p >= NPAIR) return;
    int a = p >> 5;
    int b = ps[p];
    float dx = coord[a * 3 + 0] - coord[b * 3 + 0];
    float dy = coord[a * 3 + 1] - coord[b * 3 + 1];
    float dz = coord[a * 3 + 2] - coord[b * 3 + 2];
    float d = sqrtf(dx * dx + dy * dy + dz * dz + 1e-12f);
    float cut = 0.f;
    if (d < 7.5f) { float c = cospif(d * (1.f / 15.f)); cut = c * c; }
    float invd = 1.f / d;
    const float m0 = 0.2f;
    const float m1 = 1.f / 0.7f;
    const float dmu = (m1 - m0) / 19.f;
    const float invsig = 20.f / (m1 - m0);
#pragma unroll
    for (int s = 0; s < NSENS; s++) {
        float z = (invd - (m0 + s * dmu)) * invsig;
        g_sense[p * NSENS + s] = expf(-0.5f * z * z) * cut;
    }
}

// ---------------- f0 hipnn (runs once): writes c_t, g_h[0] ----------------
__global__ void k_f0(const int* __restrict__ ps,
                     const float* __restrict__ iw, const float* __restrict__ sw,
                     const float* __restrict__ sb, const float* __restrict__ aw,
                     const float* __restrict__ ab) {
    __shared__ float ss[32 * 20];
    __shared__ float sX[32 * 5];
    __shared__ float senv[100];
    __shared__ float sy[40];
    __shared__ float sx[5];
    int a = blockIdx.x;
    int t = threadIdx.x;  // 64 threads

    for (int i = t; i < 640; i += 64) ss[i] = g_sense[a * 640 + i];
    if (t < 32) {
        int nb = ps[a * 32 + t];
#pragma unroll
        for (int f = 0; f < 5; f++) sX[t * 5 + f] = g_indf[nb * 5 + f];
    }
    if (t < 5) sx[t] = g_indf[a * 5 + t];
    __syncthreads();

    for (int e = t; e < 100; e += 64) {
        int s = e / 5, f = e % 5;
        float acc = 0.f;
        for (int k = 0; k < 32; k++) acc += ss[k * 20 + s] * sX[k * 5 + f];
        senv[e] = acc;
    }
    __syncthreads();

    if (t < 40) {
        float pre = sb[t];
        for (int e = 0; e < 100; e++) pre += senv[e] * iw[e * 40 + t];
#pragma unroll
        for (int f = 0; f < 5; f++) pre += sx[f] * sw[f * 40 + t];
        sy[t] = softplusf(pre);
    }
    __syncthreads();

    for (int l = 0; l < 3; l++) {
        float v = 0.f;
        if (t < 40) {
            v = ab[l * 40 + t];
            for (int j = 0; j < 40; j++) v += sy[j] * aw[(l * 40 + j) * 40 + t];
            v = softplusf(v);
        }
        __syncthreads();
        if (t < 40) sy[t] = v;
        __syncthreads();
    }
    if (t < 20) {
        g_ct[a * 20 + t] = sy[t];
        g_h[a * 20 + t]  = sy[20 + t];   // parity buffer 0
    }
}

// ---------------- fused per-step kernel ----------------
// SMEM (floats):
//   s_xcat [0,5120) | s_envP [5120,32320) | s_work [32320,53056)=32xSROW
//   s_nb ints [53056,54080) | s_xin [54080,54208) | s_h1w [54208,55908)
// s_envP overlay in phase 2: senvM[0,2560) sy[2560,5120) sy2[5120,7680)
// s_work overlay in GEMM:    s_wc[0,10240) s_tmp[10240,12800) s_o[12800,13440)
#define SMEM_FLOATS (5120 + 27200 + 32 * SROW + 1024 + 128 + 1700)
#define SMEM_BYTES  (SMEM_FLOATS * 4)

__global__ void __launch_bounds__(256, 1)
k_step(const int* __restrict__ ps, const float* __restrict__ x_raw, int mode,
       const float* __restrict__ h1_iw, const float* __restrict__ h1_sw,
       const float* __restrict__ h1_sb, const float* __restrict__ h1_aw,
       const float* __restrict__ h1_ab,
       const float* __restrict__ Wb,
       const float* __restrict__ pw0, const float* __restrict__ pw1,
       const float* __restrict__ pb1,
       int outcol, float* __restrict__ out, int parity) {
    extern __shared__ float sm[];
    float* s_xcat = sm;                                    // 5120
    float* s_envPf = sm + 5120;                            // 27200
    u64t*  s_envP  = (u64t*)s_envPf;                       // 13600 u64
    float* s_work = sm + 32320;                            // 20736
    int*   s_nb   = (int*)(sm + 53056);                    // 1024 ints
    float* s_xin  = sm + 54080;                            // 128
    float* s_h1w  = sm + 54208;                            // 1700
    float* s_iw = s_h1w;            // 400
    float* s_sw = s_h1w + 400;      // 20
    float* s_sb = s_h1w + 420;      // 20
    float* s_aw = s_h1w + 440;      // 1200
    float* s_ab = s_h1w + 1640;     // 60

    float* senvM = s_envPf;         // phase 2: [128][20]
    float* sy    = s_envPf + 2560;
    float* sy2   = s_envPf + 5120;
    float* s_wc  = s_work;          // GEMM W chunk (10240 floats = 64 pairs x 80 f2)
    u64t*  s_wcu = (u64t*)s_wc;
    float* s_tmp = s_work + 10240;  // 2560
    float* s_o   = s_work + 12800;  // 640

    int t  = threadIdx.x;
    int A0 = blockIdx.x * TM;
    int MB = (A0 / NATOM) * NATOM;
    int L0 = A0 - MB;
    int myc = L0 >> 5;              // my 32-atom chunk index within molecule
    const float* x0_r = g_x0 + parity * NTOT;
    float*       x0_w = g_x0 + (parity ^ 1) * NTOT;
    const float* h_r  = g_h + parity * (NTOT * NF1);
    float*       h_w  = g_h + (parity ^ 1) * (NTOT * NF1);

    // ---- stage: x_in (molecule), h -> xcat h-slots, h1 weights, my nb ----
    if (t < 128) {
        int n = MB + t;
        s_xin[t] = (mode < 2) ? x_raw[n * 2 + mode] : x0_r[n];
    }
    {
        const float4* hsrc = (const float4*)(h_r + MB * NF1);
        for (int i4 = t; i4 < 640; i4 += 256) {
            int a = i4 / 5, j = (i4 % 5) * 4;
            *(float4*)&s_xcat[a * 40 + 20 + j] = hsrc[i4];
        }
    }
    for (int i = t; i < 400;  i += 256) s_iw[i] = h1_iw[i];
    for (int i = t; i < 1200; i += 256) s_aw[i] = h1_aw[i];
    if (t < 20) { s_sw[t] = h1_sw[t]; s_sb[t] = h1_sb[t]; }
    if (t >= 64 && t < 124) s_ab[t - 64] = h1_ab[t - 64];
    for (int i = t; i < 1024; i += 256) s_nb[i] = ps[A0 * 32 + i] - MB;
    __syncthreads();

    // ---- phase 2a: env (f=1) for all 128 molecule atoms, packed s-pairs ----
    for (int cc = 0; cc < 4; cc++) {
        int c = (myc + 1 + cc) & 3;
        if (cc) __syncthreads();
        {   // stage sense for atoms [MB + c*32, +32): 32 rows x 160 float4, stride 162
            const float4* src = (const float4*)(g_sense + (size_t)(MB + c * 32) * 640);
            float4* dst = (float4*)s_work;
            for (int q = 0; q < 20; q++) {
                int i = t + q * 256;
                int row = i / 160, col = i - row * 160;
                dst[row * 162 + col] = src[i];
            }
        }
        __syncthreads();
        int aL = t >> 3;           // atom in chunk
        int r  = t & 7;            // k-lane
        int aM = c * 32 + aL;      // molecule-local atom
        u64t acc[10];
#pragma unroll
        for (int s = 0; s < 10; s++) acc[s] = 0ULL;
#pragma unroll
        for (int j = 0; j < 4; j++) {
            int k = r + j * 8;
            int nb = ps[(MB + aM) * 32 + k] - MB;
            u64t xd = packdup(s_xin[nb]);
            const ulonglong2* sp = (const ulonglong2*)(s_work + aL * SROW + k * 20);
#pragma unroll
            for (int q = 0; q < 5; q++) {
                ulonglong2 sv = sp[q];
                ffma2(acc[q * 2 + 0], sv.x, xd);
                ffma2(acc[q * 2 + 1], sv.y, xd);
            }
        }
#pragma unroll
        for (int d = 4; d >= 1; d >>= 1)
#pragma unroll
            for (int s = 0; s < 10; s++) {
                u64t o = __shfl_down_sync(0xFFFFFFFFu, acc[s], d);
                fadd2(acc[s], o);
            }
        if (r == 0) {
#pragma unroll
            for (int s = 0; s < 10; s++) {
                float lo, hi;
                unpack2(acc[s], lo, hi);
                senvM[aM * 20 + 2 * s]     = lo;
                senvM[aM * 20 + 2 * s + 1] = hi;
            }
        }
    }
    __syncthreads();

    // ---- phase 2b: x_t MLP for all 128 atoms (2 threads/atom) ----
    {
        int a  = t >> 1;
        int sh = (t & 1) * 10;
        float xo = s_xin[a];
        float pre[10];
#pragma unroll
        for (int j = 0; j < 10; j++) pre[j] = s_sb[sh + j] + xo * s_sw[sh + j];
        for (int s2 = 0; s2 < 20; s2++) {
            float ev = senvM[a * 20 + s2];
#pragma unroll
            for (int j = 0; j < 10; j++) pre[j] += ev * s_iw[s2 * 20 + sh + j];
        }
#pragma unroll
        for (int j = 0; j < 10; j++) sy[a * 20 + sh + j] = softplusf(pre[j]);
        __syncthreads();

        float* src = sy; float* dst = sy2;
        for (int l = 0; l < 3; l++) {
            float v[10];
#pragma unroll
            for (int j = 0; j < 10; j++) v[j] = s_ab[l * 20 + sh + j];
            for (int i2 = 0; i2 < 20; i2++) {
                float yv = src[a * 20 + i2];
#pragma unroll
                for (int j = 0; j < 10; j++) v[j] += yv * s_aw[(l * 20 + i2) * 20 + sh + j];
            }
            __syncthreads();
#pragma unroll
            for (int j = 0; j < 10; j++) dst[a * 20 + sh + j] = softplusf(v[j]);
            __syncthreads();
            float* tp = src; src = dst; dst = tp;
        }
#pragma unroll
        for (int j = 0; j < 10; j++) s_xcat[a * 40 + sh + j] = src[a * 20 + sh + j];
    }
    __syncthreads();

    // ---- phase 3: env (40 f) for my 32 atoms, packed s-pairs -> envP ----
    {
        int i  = t >> 3;
        int f0 = (t & 7) * 5;
        u64t acc[10][5];
#pragma unroll
        for (int sp = 0; sp < 10; sp++)
#pragma unroll
            for (int j = 0; j < 5; j++) acc[sp][j] = 0ULL;
        const float* sen = s_work + i * SROW;
        const int* nbp = s_nb + i * 32;
        for (int k = 0; k < 32; k++) {
            int nb = nbp[k];
            const float* xr = s_xcat + nb * 40 + f0;
            u64t xd[5];
#pragma unroll
            for (int j = 0; j < 5; j++) xd[j] = packdup(xr[j]);
            const ulonglong2* sk = (const ulonglong2*)(sen + k * 20);
#pragma unroll
            for (int q = 0; q < 5; q++) {
                ulonglong2 sv = sk[q];
#pragma unroll
                for (int j = 0; j < 5; j++) {
                    ffma2(acc[q * 2 + 0][j], sv.x, xd[j]);
                    ffma2(acc[q * 2 + 1][j], sv.y, xd[j]);
                }
            }
        }
#pragma unroll
        for (int sp = 0; sp < 10; sp++)
#pragma unroll
            for (int j = 0; j < 5; j++)
                s_envP[(sp * 40 + f0 + j) * EPS2 + i] = acc[sp][j];
    }
    __syncthreads();   // sense reads done + envP visible; s_work free for s_wc

    // ---- phase 4: GEMM via packed e-pairs: 400 pairs, chunks of 64 ----
    u64t accA[5], accB[5];
#pragma unroll
    for (int j = 0; j < 5; j++) { accA[j] = 0ULL; accB[j] = 0ULL; }
    int g0 = (t & 15) * 5;      // g-group start in u64 units
    int i0 = (t >> 4) * 2;      // atom pair start
    const float4* W4 = (const float4*)g_wpair;

    for (int i = t; i < 2560; i += 256) ((float4*)s_wc)[i] = W4[i];  // chunk 0 (64 pairs)
    __syncthreads();

    for (int c = 0; c < 7; c++) {
        int p0 = c * 64;
        int plen = (c < 6) ? 64 : 16;
        float4 pf[10];
        int nb4 = 0, pbase = 0;
        if (c < 6) {
            nb4 = ((c + 1 < 6) ? 64 : 16) * 40;
            pbase = (p0 + 64) * 40;
#pragma unroll
            for (int q = 0; q < 10; q++) {
                int i = t + q * 256;
                if (i < nb4) pf[q] = W4[pbase + i];
            }
        }
        for (int pp = 0; pp < plen; pp++) {
            ulonglong2 av = *(const ulonglong2*)&s_envP[(p0 + pp) * EPS2 + i0];
            const u64t* wr = &s_wcu[pp * 80 + g0];
            u64t b0 = wr[0], b1 = wr[1], b2 = wr[2], b3 = wr[3], b4 = wr[4];
            ffma2(accA[0], av.x, b0); ffma2(accB[0], av.y, b0);
            ffma2(accA[1], av.x, b1); ffma2(accB[1], av.y, b1);
            ffma2(accA[2], av.x, b2); ffma2(accB[2], av.y, b2);
            ffma2(accA[3], av.x, b3); ffma2(accB[3], av.y, b3);
            ffma2(accA[4], av.x, b4); ffma2(accB[4], av.y, b4);
        }
        __syncthreads();
        if (c < 6) {
#pragma unroll
            for (int q = 0; q < 10; q++) {
                int i = t + q * 256;
                if (i < nb4) ((float4*)s_wc)[i] = pf[q];
            }
            __syncthreads();
        }
    }

    // self term: packed f-pairs from xcat (contiguous) x g_wspair
    {
        const u64t* xc0p = (const u64t*)(s_xcat + (L0 + i0) * 40);
        const u64t* xc1p = (const u64t*)(s_xcat + (L0 + i0 + 1) * 40);
        const u64t* wsp = (const u64t*)g_wspair;
#pragma unroll 4
        for (int fp = 0; fp < 20; fp++) {
            u64t a0p = xc0p[fp];
            u64t a1p = xc1p[fp];
            const u64t* wr = wsp + fp * 80 + g0;
#pragma unroll
            for (int j = 0; j < 5; j++) {
                u64t w = wr[j];
                ffma2(accA[j], a0p, w);
                ffma2(accB[j], a1p, w);
            }
        }
    }

    // unpack + bias -> s_tmp
    {
        float* d0 = &s_tmp[(i0 + 0) * 80 + g0];
        float* d1 = &s_tmp[(i0 + 1) * 80 + g0];
#pragma unroll
        for (int j = 0; j < 5; j++) {
            float b = Wb[g0 + j];
            float lo, hi;
            unpack2(accA[j], lo, hi);
            d0[j] = lo + hi + b;
            unpack2(accB[j], lo, hi);
            d1[j] = lo + hi + b;
        }
    }
    __syncthreads();

    // ---- phase 5: gates ----
    for (int idx = t; idx < TM * 20; idx += 256) {
        int i = idx / 20, j = idx % 20;
        int a = A0 + i;
        float t0v = s_tmp[i * 80 + j * 4 + 0];
        float t1v = s_tmp[i * 80 + j * 4 + 1];
        float t2v = s_tmp[i * 80 + j * 4 + 2];
        float t3v = s_tmp[i * 80 + j * 4 + 3];
        float o  = sigmoidf(t3v);
        float cn = sigmoidf(t1v) * g_ct[a * 20 + j] + sigmoidf(t0v) * tanhf(t2v);
        g_ct[a * 20 + j] = cn;
        h_w[a * 20 + j]  = o * tanhf(cn);
        s_o[i * 20 + j] = o;
    }
    __syncthreads();

    // ---- x0 epilogue (+ output column for steps 2..4) ----
    if (t < TM) {
        int a = A0 + t;
        float x0v = pb1[0];
#pragma unroll
        for (int f = 0; f < 5; f++)  x0v += g_indf[a * 5 + f] * pw0[f];
#pragma unroll
        for (int j = 0; j < 20; j++) x0v += s_o[t * 20 + j] * pw1[j];
        x0_w[a] = x0v;
        if (outcol >= 0) out[a * 3 + outcol] = x0v;
    }
}

// ---------------- host ----------------
extern "C" void kernel_launch(void* const* d_in, const int* in_sizes, int n_in,
                              void* d_out, int out_size) {
    const int*   species = (const int*)d_in[0];
    const float* coords  = (const float*)d_in[1];
    const float* x_h     = (const float*)d_in[2];
    const float* x_raw   = (const float*)d_in[3];
    const int*   ps      = (const int*)d_in[5];
    const float* h0_iw   = (const float*)d_in[6];
    const float* h0_sw   = (const float*)d_in[7];
    const float* h0_sb   = (const float*)d_in[8];
    const float* h0_aw   = (const float*)d_in[9];
    const float* h0_ab   = (const float*)d_in[10];
    const float* h1_iw   = (const float*)d_in[11];
    const float* h1_sw   = (const float*)d_in[12];
    const float* h1_sb   = (const float*)d_in[13];
    const float* h1_aw   = (const float*)d_in[14];
    const float* h1_ab   = (const float*)d_in[15];
    const float* W_iw    = (const float*)d_in[16];
    const float* W_sw    = (const float*)d_in[17];
    const float* W_sb    = (const float*)d_in[18];
    const float* pw0     = (const float*)d_in[19];
    const float* pw1     = (const float*)d_in[20];
    const float* pb1     = (const float*)d_in[21];
    float* out = (float*)d_out;

    cudaFuncSetAttribute(k_step, cudaFuncAttributeMaxDynamicSharedMemorySize, SMEM_BYTES);

    k_indf<<<(NTOT + 255) / 256, 256>>>(species, x_h);
    k_wprep<<<(33600 + 255) / 256, 256>>>(W_iw, W_sw);
    k_sense<<<NPAIR / 256, 256>>>(coords, ps);
    k_f0<<<NTOT, 64>>>(ps, h0_iw, h0_sw, h0_sb, h0_aw, h0_ab);

    for (int s = 0; s < 5; s++) {
        int mode = (s < 2) ? s : 2;
        int outcol = (s >= 2) ? (s - 2) : -1;
        k_step<<<NTOT / TM, 256, SMEM_BYTES>>>(ps, x_raw, mode,
                                               h1_iw, h1_sw, h1_sb, h1_aw, h1_ab,
                                               W_sb,
                                               pw0, pw1, pb1,
                                               outcol, out, s & 1);
    }
}

// round 8
// speedup vs baseline: 2.2910x; 1.0208x over previous
#include <cuda_runtime.h>
#include <math.h>

#define NMOL   32
#define NATOM  128
#define DEG    32
#define NTOT   4096
#define NPAIR  131072
#define NSENS  20
#define NF1    20
#define TM     32          // atoms owned per k_step block
#define EPS2   34          // envP row stride in u64 units (even -> 16B-aligned pairs)
#define SROW   648         // padded sense row (floats) = 162 float4

typedef unsigned long long u64t;

// ---------------- scratch (device globals; no allocation) ----------------
__device__ float  g_sense[NPAIR * NSENS];    // [pair][s]
__device__ float  g_indf [NTOT * 5];         // [atom][5]
__device__ float  g_ct   [NTOT * NF1];       // in-place (owner block only)
__device__ float  g_h    [2 * NTOT * NF1];   // parity double buffer
__device__ float  g_x0   [2 * NTOT];         // parity double buffer
__device__ float2 g_wpair [400 * 80];        // Wint paired over (s_even, s_odd)
__device__ float2 g_wspair[20 * 80];         // Wself paired over (f_even, f_odd)

__device__ __forceinline__ float softplusf(float x) {
    return fmaxf(x, 0.f) + log1pf(expf(-fabsf(x)));
}
__device__ __forceinline__ float sigmoidf(float x) {
    return 1.f / (1.f + expf(-x));
}
__device__ __forceinline__ u64t packdup(float x) {
    u64t r; asm("mov.b64 %0, {%1, %1};" : "=l"(r) : "f"(x)); return r;
}
__device__ __forceinline__ void ffma2(u64t& d, u64t a, u64t b) {
    asm("fma.rn.f32x2 %0, %1, %2, %0;" : "+l"(d) : "l"(a), "l"(b));
}
__device__ __forceinline__ void fadd2(u64t& d, u64t a) {
    asm("add.rn.f32x2 %0, %0, %1;" : "+l"(d) : "l"(a));
}
__device__ __forceinline__ void unpack2(u64t v, float& lo, float& hi) {
    asm("mov.b64 {%0, %1}, %2;" : "=f"(lo), "=f"(hi) : "l"(v));
}

// ---------------- one-time prep (merged): sense + indf + weight pairing ----------------
__global__ void k_prep(const int* __restrict__ species, const float* __restrict__ x_h,
                       const float* __restrict__ coord, const int* __restrict__ ps,
                       const float* __restrict__ Wint, const float* __restrict__ Wself) {
    int p = blockIdx.x * 256 + threadIdx.x;   // [0, NPAIR)

    // ---- sense via anchored Gaussian recurrence (3-4 expf instead of 20) ----
    {
        int a = p >> 5;
        int b = ps[p];
        float dx = coord[a * 3 + 0] - coord[b * 3 + 0];
        float dy = coord[a * 3 + 1] - coord[b * 3 + 1];
        float dz = coord[a * 3 + 2] - coord[b * 3 + 2];
        float d = sqrtf(dx * dx + dy * dy + dz * dz + 1e-12f);
        float cut = 0.f;
        if (d < 7.5f) { float c = cospif(d * (1.f / 15.f)); cut = c * c; }
        const float m0 = 0.2f;
        const float m1 = 1.f / 0.7f;
        const float invsig = 20.f / (m1 - m0);
        const float delta = 20.f / 19.f;          // dmu * invsig, exact
        float z0 = (1.f / d - m0) * invsig;

        float ss = floorf(z0 / delta + 0.5f);
        ss = fminf(fmaxf(ss, 0.f), 19.f);
        int sstar = (int)ss;
        float zs = z0 - ss * delta;

        float Cd = expf(-delta * delta);
        float E  = cut * expf(-0.5f * zs * zs);
        float* o = g_sense + (size_t)p * 20;
        o[sstar] = E;
        // up chain (factors <= 1 by peak anchoring)
        float Eu = E;
        float uu = expf(delta * zs - 0.5f * delta * delta);
        for (int s = sstar + 1; s < 20; s++) { Eu *= uu; uu *= Cd; o[s] = Eu; }
        // down chain
        float Ed = E;
        float dd = expf(-delta * zs - 0.5f * delta * delta);
        for (int s = sstar - 1; s >= 0; s--) { Ed *= dd; dd *= Cd; o[s] = Ed; }
    }

    // ---- indf ----
    if (p < NTOT) {
        int sp = species[p];
        g_indf[p * 5 + 0] = (sp == 1) ? 1.f : 0.f;
        g_indf[p * 5 + 1] = (sp == 8) ? 1.f : 0.f;
        g_indf[p * 5 + 2] = x_h[p * 3 + 0];
        g_indf[p * 5 + 3] = x_h[p * 3 + 1];
        g_indf[p * 5 + 4] = x_h[p * 3 + 2];
    }

    // ---- weight pairing ----
    if (p < 32000) {
        int pr = p / 80, g = p % 80;
        int s2 = pr / 40, f = pr % 40;
        int lo = 2 * s2 * 40 + f;
        g_wpair[p] = make_float2(Wint[lo * 80 + g], Wint[(lo + 40) * 80 + g]);
    } else if (p < 32000 + 1600) {
        int i2 = p - 32000;
        int fp = i2 / 80, g = i2 % 80;
        g_wspair[i2] = make_float2(Wself[(2 * fp) * 80 + g], Wself[(2 * fp + 1) * 80 + g]);
    }
}

// ---------------- f0 hipnn (runs once, block-tiled): writes c_t, g_h[0] ----------------
#define SMEM_F0_FLOATS 37448
#define SMEM_F0_BYTES  (SMEM_F0_FLOATS * 4)

__global__ void __launch_bounds__(256, 1)
k_f0(const int* __restrict__ ps,
     const float* __restrict__ iw, const float* __restrict__ sw,
     const float* __restrict__ sb, const float* __restrict__ aw,
     const float* __restrict__ ab) {
    extern __shared__ float sm[];
    float* s_sense = sm;
    float* s_senv  = sm + 20736;
    float* s_indf  = sm + 24064;
    float* s_iw    = sm + 24704;
    float* s_sw    = sm + 28704;
    float* s_sb    = sm + 28904;
    float* s_aw    = sm + 28944;
    float* s_ab    = sm + 33744;
    float* s_sy    = sm + 33864;
    float* s_sy2   = sm + 35144;
    int*   s_nb    = (int*)(sm + 36424);

    int t  = threadIdx.x;
    int A0 = blockIdx.x * TM;
    int MB = (A0 / NATOM) * NATOM;
    int L0 = A0 - MB;

    // ---- stage ----
    for (int i = t; i < 1024; i += 256) s_nb[i] = ps[A0 * 32 + i] - MB;
    for (int i = t; i < 640;  i += 256) s_indf[i] = g_indf[MB * 5 + i];
    for (int i = t; i < 4000; i += 256) s_iw[i] = iw[i];
    for (int i = t; i < 4800; i += 256) s_aw[i] = aw[i];
    if (t < 200) s_sw[t] = sw[t];
    if (t >= 216 && t < 256) s_sb[t - 216] = sb[t - 216];
    for (int i = t; i < 120; i += 256) s_ab[i] = ab[i];
    {
        const float4* src = (const float4*)(g_sense + (size_t)A0 * 640);
        float4* dst = (float4*)s_sense;
        for (int q = 0; q < 20; q++) {
            int i = t + q * 256;
            int row = i / 160, col = i - row * 160;
            dst[row * 162 + col] = src[i];
        }
    }
    __syncthreads();

    // ---- env: 8 k-lanes per atom, packed s-pairs, shuffle-reduce ----
    {
        int aL = t >> 3;
        int r  = t & 7;
        u64t acc[10][5];
#pragma unroll
        for (int q = 0; q < 10; q++)
#pragma unroll
            for (int f = 0; f < 5; f++) acc[q][f] = 0ULL;
#pragma unroll
        for (int j = 0; j < 4; j++) {
            int k = r + j * 8;
            int nb = s_nb[aL * 32 + k];
            const float* xp = s_indf + nb * 5;
            u64t xd[5];
#pragma unroll
            for (int f = 0; f < 5; f++) xd[f] = packdup(xp[f]);
            const ulonglong2* spp = (const ulonglong2*)(s_sense + aL * SROW + k * 20);
#pragma unroll
            for (int q = 0; q < 5; q++) {
                ulonglong2 sv = spp[q];
#pragma unroll
                for (int f = 0; f < 5; f++) {
                    ffma2(acc[q * 2 + 0][f], sv.x, xd[f]);
                    ffma2(acc[q * 2 + 1][f], sv.y, xd[f]);
                }
            }
        }
#pragma unroll
        for (int d = 4; d >= 1; d >>= 1)
#pragma unroll
            for (int q = 0; q < 10; q++)
#pragma unroll
                for (int f = 0; f < 5; f++) {
                    u64t o = __shfl_down_sync(0xFFFFFFFFu, acc[q][f], d);
                    fadd2(acc[q][f], o);
                }
        if (r == 0) {
#pragma unroll
            for (int q = 0; q < 10; q++)
#pragma unroll
                for (int f = 0; f < 5; f++) {
                    float lo, hi;
                    unpack2(acc[q][f], lo, hi);
                    s_senv[aL * 104 + (2 * q)     * 5 + f] = lo;
                    s_senv[aL * 104 + (2 * q + 1) * 5 + f] = hi;
                }
        }
    }
    __syncthreads();

    // ---- MLP: 8 threads/atom, 5 outputs each (40 total) ----
    {
        int a  = t >> 3;
        int j0 = (t & 7) * 5;
        float pre[5];
#pragma unroll
        for (int jj = 0; jj < 5; jj++) pre[jj] = s_sb[j0 + jj];
        const float* xo = s_indf + (L0 + a) * 5;
#pragma unroll
        for (int f = 0; f < 5; f++) {
            float xv = xo[f];
#pragma unroll
            for (int jj = 0; jj < 5; jj++) pre[jj] += xv * s_sw[f * 40 + j0 + jj];
        }
        for (int e = 0; e < 100; e++) {
            float ev = s_senv[a * 104 + e];
#pragma unroll
            for (int jj = 0; jj < 5; jj++) pre[jj] += ev * s_iw[e * 40 + j0 + jj];
        }
#pragma unroll
        for (int jj = 0; jj < 5; jj++) s_sy[a * 40 + j0 + jj] = softplusf(pre[jj]);
        __syncthreads();

        float* src = s_sy; float* dst = s_sy2;
        for (int l = 0; l < 3; l++) {
            float v[5];
#pragma unroll
            for (int jj = 0; jj < 5; jj++) v[jj] = s_ab[l * 40 + j0 + jj];
            for (int i = 0; i < 40; i++) {
                float yv = src[a * 40 + i];
#pragma unroll
                for (int jj = 0; jj < 5; jj++) v[jj] += yv * s_aw[l * 1600 + i * 40 + j0 + jj];
            }
            __syncthreads();
#pragma unroll
            for (int jj = 0; jj < 5; jj++) dst[a * 40 + j0 + jj] = softplusf(v[jj]);
            __syncthreads();
            float* tp = src; src = dst; dst = tp;
        }
        // after 3 layers result is in src (== s_sy2)
        for (int idx = t; idx < 640; idx += 256) {
            int a2 = idx / 20, j = idx % 20;
            g_ct[(A0 + a2) * 20 + j] = src[a2 * 40 + j];
            g_h[(A0 + a2) * 20 + j]  = src[a2 * 40 + 20 + j];
        }
    }
}

// ---------------- fused per-step kernel ----------------
#define SMEM_FLOATS (5120 + 27200 + 32 * SROW + 1024 + 128 + 1700)
#define SMEM_BYTES  (SMEM_FLOATS * 4)

__global__ void __launch_bounds__(256, 1)
k_step(const int* __restrict__ ps, const float* __restrict__ x_raw, int mode,
       const float* __restrict__ h1_iw, const float* __restrict__ h1_sw,
       const float* __restrict__ h1_sb, const float* __restrict__ h1_aw,
       const float* __restrict__ h1_ab,
       const float* __restrict__ Wb,
       const float* __restrict__ pw0, const float* __restrict__ pw1,
       const float* __restrict__ pb1,
       int outcol, float* __restrict__ out, int parity) {
    extern __shared__ float sm[];
    float* s_xcat = sm;                                    // 5120
    float* s_envPf = sm + 5120;                            // 27200
    u64t*  s_envP  = (u64t*)s_envPf;                       // 13600 u64
    float* s_work = sm + 32320;                            // 20736
    int*   s_nb   = (int*)(sm + 53056);                    // 1024 ints
    float* s_xin  = sm + 54080;                            // 128
    float* s_h1w  = sm + 54208;                            // 1700
    float* s_iw = s_h1w;            // 400
    float* s_sw = s_h1w + 400;      // 20
    float* s_sb = s_h1w + 420;      // 20
    float* s_aw = s_h1w + 440;      // 1200
    float* s_ab = s_h1w + 1640;     // 60

    float* senvM = s_envPf;         // phase 2: [128][20]
    float* sy    = s_envPf + 2560;
    float* sy2   = s_envPf + 5120;
    float* s_wc  = s_work;          // GEMM W chunk (10240 floats = 64 pairs x 80 f2)
    u64t*  s_wcu = (u64t*)s_wc;
    float* s_tmp = s_work + 10240;  // 2560
    float* s_o   = s_work + 12800;  // 640

    int t  = threadIdx.x;
    int A0 = blockIdx.x * TM;
    int MB = (A0 / NATOM) * NATOM;
    int L0 = A0 - MB;
    int myc = L0 >> 5;              // my 32-atom chunk index within molecule
    const float* x0_r = g_x0 + parity * NTOT;
    float*       x0_w = g_x0 + (parity ^ 1) * NTOT;
    const float* h_r  = g_h + parity * (NTOT * NF1);
    float*       h_w  = g_h + (parity ^ 1) * (NTOT * NF1);

    // ---- stage: x_in (molecule), h -> xcat h-slots, h1 weights, my nb ----
    if (t < 128) {
        int n = MB + t;
        s_xin[t] = (mode < 2) ? x_raw[n * 2 + mode] : x0_r[n];
    }
    {
        const float4* hsrc = (const float4*)(h_r + MB * NF1);
        for (int i4 = t; i4 < 640; i4 += 256) {
            int a = i4 / 5, j = (i4 % 5) * 4;
            *(float4*)&s_xcat[a * 40 + 20 + j] = hsrc[i4];
        }
    }
    for (int i = t; i < 400;  i += 256) s_iw[i] = h1_iw[i];
    for (int i = t; i < 1200; i += 256) s_aw[i] = h1_aw[i];
    if (t < 20) { s_sw[t] = h1_sw[t]; s_sb[t] = h1_sb[t]; }
    if (t >= 64 && t < 124) s_ab[t - 64] = h1_ab[t - 64];
    for (int i = t; i < 1024; i += 256) s_nb[i] = ps[A0 * 32 + i] - MB;
    __syncthreads();

    // ---- phase 2a: env (f=1) for all 128 molecule atoms, packed s-pairs ----
    for (int cc = 0; cc < 4; cc++) {
        int c = (myc + 1 + cc) & 3;
        if (cc) __syncthreads();
        {
            const float4* src = (const float4*)(g_sense + (size_t)(MB + c * 32) * 640);
            float4* dst = (float4*)s_work;
            for (int q = 0; q < 20; q++) {
                int i = t + q * 256;
                int row = i / 160, col = i - row * 160;
                dst[row * 162 + col] = src[i];
            }
        }
        __syncthreads();
        int aL = t >> 3;
        int r  = t & 7;
        int aM = c * 32 + aL;
        u64t acc[10];
#pragma unroll
        for (int s = 0; s < 10; s++) acc[s] = 0ULL;
#pragma unroll
        for (int j = 0; j < 4; j++) {
            int k = r + j * 8;
            int nb = ps[(MB + aM) * 32 + k] - MB;
            u64t xd = packdup(s_xin[nb]);
            const ulonglong2* sp = (const ulonglong2*)(s_work + aL * SROW + k * 20);
#pragma unroll
            for (int q = 0; q < 5; q++) {
                ulonglong2 sv = sp[q];
                ffma2(acc[q * 2 + 0], sv.x, xd);
                ffma2(acc[q * 2 + 1], sv.y, xd);
            }
        }
#pragma unroll
        for (int d = 4; d >= 1; d >>= 1)
#pragma unroll
            for (int s = 0; s < 10; s++) {
                u64t o = __shfl_down_sync(0xFFFFFFFFu, acc[s], d);
                fadd2(acc[s], o);
            }
        if (r == 0) {
#pragma unroll
            for (int s = 0; s < 10; s++) {
                float lo, hi;
                unpack2(acc[s], lo, hi);
                senvM[aM * 20 + 2 * s]     = lo;
                senvM[aM * 20 + 2 * s + 1] = hi;
            }
        }
    }
    __syncthreads();

    // ---- phase 2b: x_t MLP for all 128 atoms (2 threads/atom) ----
    {
        int a  = t >> 1;
        int sh = (t & 1) * 10;
        float xo = s_xin[a];
        float pre[10];
#pragma unroll
        for (int j = 0; j < 10; j++) pre[j] = s_sb[sh + j] + xo * s_sw[sh + j];
        for (int s2 = 0; s2 < 20; s2++) {
            float ev = senvM[a * 20 + s2];
#pragma unroll
            for (int j = 0; j < 10; j++) pre[j] += ev * s_iw[s2 * 20 + sh + j];
        }
#pragma unroll
        for (int j = 0; j < 10; j++) sy[a * 20 + sh + j] = softplusf(pre[j]);
        __syncthreads();

        float* src = sy; float* dst = sy2;
        for (int l = 0; l < 3; l++) {
            float v[10];
#pragma unroll
            for (int j = 0; j < 10; j++) v[j] = s_ab[l * 20 + sh + j];
            for (int i2 = 0; i2 < 20; i2++) {
                float yv = src[a * 20 + i2];
#pragma unroll
                for (int j = 0; j < 10; j++) v[j] += yv * s_aw[(l * 20 + i2) * 20 + sh + j];
            }
            __syncthreads();
#pragma unroll
            for (int j = 0; j < 10; j++) dst[a * 20 + sh + j] = softplusf(v[j]);
            __syncthreads();
            float* tp = src; src = dst; dst = tp;
        }
#pragma unroll
        for (int j = 0; j < 10; j++) s_xcat[a * 40 + sh + j] = src[a * 20 + sh + j];
    }
    __syncthreads();

    // ---- phase 3: env (40 f) for my 32 atoms, packed s-pairs -> envP ----
    {
        int i  = t >> 3;
        int f0 = (t & 7) * 5;
        u64t acc[10][5];
#pragma unroll
        for (int sp = 0; sp < 10; sp++)
#pragma unroll
            for (int j = 0; j < 5; j++) acc[sp][j] = 0ULL;
        const float* sen = s_work + i * SROW;
        const int* nbp = s_nb + i * 32;
        for (int k = 0; k < 32; k++) {
            int nb = nbp[k];
            const float* xr = s_xcat + nb * 40 + f0;
            u64t xd[5];
#pragma unroll
            for (int j = 0; j < 5; j++) xd[j] = packdup(xr[j]);
            const ulonglong2* sk = (const ulonglong2*)(sen + k * 20);
#pragma unroll
            for (int q = 0; q < 5; q++) {
                ulonglong2 sv = sk[q];
#pragma unroll
                for (int j = 0; j < 5; j++) {
                    ffma2(acc[q * 2 + 0][j], sv.x, xd[j]);
                    ffma2(acc[q * 2 + 1][j], sv.y, xd[j]);
                }
            }
        }
#pragma unroll
        for (int sp = 0; sp < 10; sp++)
#pragma unroll
            for (int j = 0; j < 5; j++)
                s_envP[(sp * 40 + f0 + j) * EPS2 + i] = acc[sp][j];
    }
    __syncthreads();

    // ---- phase 4: GEMM via packed e-pairs: 400 pairs, chunks of 64 ----
    u64t accA[5], accB[5];
#pragma unroll
    for (int j = 0; j < 5; j++) { accA[j] = 0ULL; accB[j] = 0ULL; }
    int g0 = (t & 15) * 5;
    int i0 = (t >> 4) * 2;
    const float4* W4 = (const float4*)g_wpair;

    for (int i = t; i < 2560; i += 256) ((float4*)s_wc)[i] = W4[i];
    __syncthreads();

    for (int c = 0; c < 7; c++) {
        int p0 = c * 64;
        int plen = (c < 6) ? 64 : 16;
        float4 pf[10];
        int nb4 = 0, pbase = 0;
        if (c < 6) {
            nb4 = ((c + 1 < 6) ? 64 : 16) * 40;
            pbase = (p0 + 64) * 40;
#pragma unroll
            for (int q = 0; q < 10; q++) {
                int i = t + q * 256;
                if (i < nb4) pf[q] = W4[pbase + i];
            }
        }
        for (int pp = 0; pp < plen; pp++) {
            ulonglong2 av = *(const ulonglong2*)&s_envP[(p0 + pp) * EPS2 + i0];
            const u64t* wr = &s_wcu[pp * 80 + g0];
            u64t b0 = wr[0], b1 = wr[1], b2 = wr[2], b3 = wr[3], b4 = wr[4];
            ffma2(accA[0], av.x, b0); ffma2(accB[0], av.y, b0);
            ffma2(accA[1], av.x, b1); ffma2(accB[1], av.y, b1);
            ffma2(accA[2], av.x, b2); ffma2(accB[2], av.y, b2);
            ffma2(accA[3], av.x, b3); ffma2(accB[3], av.y, b3);
            ffma2(accA[4], av.x, b4); ffma2(accB[4], av.y, b4);
        }
        __syncthreads();
        if (c < 6) {
#pragma unroll
            for (int q = 0; q < 10; q++) {
                int i = t + q * 256;
                if (i < nb4) ((float4*)s_wc)[i] = pf[q];
            }
            __syncthreads();
        }
    }

    // self term: packed f-pairs from xcat x g_wspair
    {
        const u64t* xc0p = (const u64t*)(s_xcat + (L0 + i0) * 40);
        const u64t* xc1p = (const u64t*)(s_xcat + (L0 + i0 + 1) * 40);
        const u64t* wsp = (const u64t*)g_wspair;
#pragma unroll 4
        for (int fp = 0; fp < 20; fp++) {
            u64t a0p = xc0p[fp];
            u64t a1p = xc1p[fp];
            const u64t* wr = wsp + fp * 80 + g0;
#pragma unroll
            for (int j = 0; j < 5; j++) {
                u64t w = wr[j];
                ffma2(accA[j], a0p, w);
                ffma2(accB[j], a1p, w);
            }
        }
    }

    // unpack + bias -> s_tmp
    {
        float* d0 = &s_tmp[(i0 + 0) * 80 + g0];
        float* d1 = &s_tmp[(i0 + 1) * 80 + g0];
#pragma unroll
        for (int j = 0; j < 5; j++) {
            float b = Wb[g0 + j];
            float lo, hi;
            unpack2(accA[j], lo, hi);
            d0[j] = lo + hi + b;
            unpack2(accB[j], lo, hi);
            d1[j] = lo + hi + b;
        }
    }
    __syncthreads();

    // ---- phase 5: gates ----
    for (int idx = t; idx < TM * 20; idx += 256) {
        int i = idx / 20, j = idx % 20;
        int a = A0 + i;
        float t0v = s_tmp[i * 80 + j * 4 + 0];
        float t1v = s_tmp[i * 80 + j * 4 + 1];
        float t2v = s_tmp[i * 80 + j * 4 + 2];
        float t3v = s_tmp[i * 80 + j * 4 + 3];
        float o  = sigmoidf(t3v);
        float cn = sigmoidf(t1v) * g_ct[a * 20 + j] + sigmoidf(t0v) * tanhf(t2v);
        g_ct[a * 20 + j] = cn;
        h_w[a * 20 + j]  = o * tanhf(cn);
        s_o[i * 20 + j] = o;
    }
    __syncthreads();

    // ---- x0 epilogue (+ output column for steps 2..4) ----
    if (t < TM) {
        int a = A0 + t;
        float x0v = pb1[0];
#pragma unroll
        for (int f = 0; f < 5; f++)  x0v += g_indf[a * 5 + f] * pw0[f];
#pragma unroll
        for (int j = 0; j < 20; j++) x0v += s_o[t * 20 + j] * pw1[j];
        x0_w[a] = x0v;
        if (outcol >= 0) out[a * 3 + outcol] = x0v;
    }
}

// ---------------- host ----------------
extern "C" void kernel_launch(void* const* d_in, const int* in_sizes, int n_in,
                              void* d_out, int out_size) {
    const int*   species = (const int*)d_in[0];
    const float* coords  = (const float*)d_in[1];
    const float* x_h     = (const float*)d_in[2];
    const float* x_raw   = (const float*)d_in[3];
    const int*   ps      = (const int*)d_in[5];
    const float* h0_iw   = (const float*)d_in[6];
    const float* h0_sw   = (const float*)d_in[7];
    const float* h0_sb   = (const float*)d_in[8];
    const float* h0_aw   = (const float*)d_in[9];
    const float* h0_ab   = (const float*)d_in[10];
    const float* h1_iw   = (const float*)d_in[11];
    const float* h1_sw   = (const float*)d_in[12];
    const float* h1_sb   = (const float*)d_in[13];
    const float* h1_aw   = (const float*)d_in[14];
    const float* h1_ab   = (const float*)d_in[15];
    const float* W_iw    = (const float*)d_in[16];
    const float* W_sw    = (const float*)d_in[17];
    const float* W_sb    = (const float*)d_in[18];
    const float* pw0     = (const float*)d_in[19];
    const float* pw1     = (const float*)d_in[20];
    const float* pb1     = (const float*)d_in[21];
    float* out = (float*)d_out;

    cudaFuncSetAttribute(k_step, cudaFuncAttributeMaxDynamicSharedMemorySize, SMEM_BYTES);
    cudaFuncSetAttribute(k_f0,   cudaFuncAttributeMaxDynamicSharedMemorySize, SMEM_F0_BYTES);

    k_prep<<<NPAIR / 256, 256>>>(species, x_h, coords, ps, W_iw, W_sw);
    k_f0<<<NTOT / TM, 256, SMEM_F0_BYTES>>>(ps, h0_iw, h0_sw, h0_sb, h0_aw, h0_ab);

    for (int s = 0; s < 5; s++) {
        int mode = (s < 2) ? s : 2;
        int outcol = (s >= 2) ? (s - 2) : -1;
        k_step<<<NTOT / TM, 256, SMEM_BYTES>>>(ps, x_raw, mode,
                                               h1_iw, h1_sw, h1_sb, h1_aw, h1_ab,
                                               W_sb,
                                               pw0, pw1, pb1,
                                               outcol, out, s & 1);
    }
}